// round 4
// baseline (speedup 1.0000x reference)
#include <cuda_runtime.h>

#define VOCAB  32000
#define EMBED  512
#define HIDDEN 512
#define BATCH  64
#define TSTEPS 64

// -------- persistent scratch (no allocs allowed) --------
__device__ float g_h[2][BATCH * HIDDEN];
__device__ float g_c[BATCH * HIDDEN];
__device__ unsigned long long g_amax[TSTEPS * BATCH];

// monotone float -> uint mapping for atomicMax-based argmax
__device__ __forceinline__ unsigned int ford(float f) {
    unsigned int u = __float_as_uint(f);
    return (u & 0x80000000u) ? ~u : (u | 0x80000000u);
}

// ---------------- init: copy initial state, zero argmax slots ----------------
__global__ void init_kernel(const float* __restrict__ hidden,
                            const float* __restrict__ cell) {
    int i = blockIdx.x * blockDim.x + threadIdx.x;
    if (i < BATCH * HIDDEN) {
        g_h[0][i] = hidden[i];
        g_c[i]    = cell[i];
    }
    if (i < TSTEPS * BATCH) g_amax[i] = 0ull;
}

// ---------------- LSTM step: gates GEMM + cell update ----------------
// grid = 128 CTAs, each owns 4 hidden units (16 gate rows) x all 64 batches.
// thread (m = tid&63, q = tid>>6) computes i,f,g,o for (batch m, unit j0+q)
// and performs the cell update in-register.
__global__ __launch_bounds__(256) void lstm_step_kernel(
    const float* __restrict__ embedding,
    const float* __restrict__ w_ih,
    const float* __restrict__ w_hh,
    const float* __restrict__ b_ih,
    const float* __restrict__ b_hh,
    const int*   __restrict__ start_tok,
    int t)
{
    __shared__ float As[128][64];   // [k][b]   32 KB
    __shared__ float Ws[128][16];   // [k][r']   8 KB ; r' = q*4 + gate
    __shared__ int   toks[BATCH];

    const int tid = threadIdx.x;
    const int j0  = blockIdx.x * 4;
    const int rb  = t & 1;          // h buffer to read
    const int wb  = rb ^ 1;         // h buffer to write

    if (tid < BATCH) {
        if (t == 0) toks[tid] = *start_tok;
        else {
            unsigned long long key = g_amax[(t - 1) * BATCH + tid];
            toks[tid] = (int)(~((unsigned int)(key & 0xFFFFFFFFull)));
        }
    }
    __syncthreads();

    const int m = tid & 63;
    const int q = tid >> 6;         // 0..3 : unit within CTA
    float acc0 = 0.f, acc1 = 0.f, acc2 = 0.f, acc3 = 0.f;

    for (int kc = 0; kc < 8; kc++) {
        const int kbase = kc * 128;
        // ---- load activation chunk A[b][kbase..kbase+127] -> As[k][b]
        {
            const int b   = tid >> 2;
            const int klo = (tid & 3) * 32;
            const float* src = (kbase < EMBED)
                ? embedding + (size_t)toks[b] * EMBED + kbase + klo
                : g_h[rb] + b * HIDDEN + (kbase - EMBED) + klo;
            #pragma unroll
            for (int i = 0; i < 8; i++) {
                float4 v = *(const float4*)(src + i * 4);
                int k = klo + i * 4;
                As[k][b] = v.x; As[k+1][b] = v.y; As[k+2][b] = v.z; As[k+3][b] = v.w;
            }
        }
        // ---- load weight chunk: 16 gate rows x 128 k -> Ws[k][r']
        {
            const int rp  = tid >> 4;            // r' = 0..15
            const int klo = (tid & 15) * 8;
            const int R   = (rp & 3) * HIDDEN + j0 + (rp >> 2); // gate*512 + unit
            const float* src = (kbase < EMBED)
                ? w_ih + (size_t)R * EMBED + kbase + klo
                : w_hh + (size_t)R * HIDDEN + (kbase - EMBED) + klo;
            #pragma unroll
            for (int i = 0; i < 2; i++) {
                float4 v = *(const float4*)(src + i * 4);
                int k = klo + i * 4;
                Ws[k][rp] = v.x; Ws[k+1][rp] = v.y; Ws[k+2][rp] = v.z; Ws[k+3][rp] = v.w;
            }
        }
        __syncthreads();

        #pragma unroll 16
        for (int k = 0; k < 128; k++) {
            float  a = As[k][m];
            float4 w = *(const float4*)&Ws[k][q * 4];
            acc0 += a * w.x; acc1 += a * w.y; acc2 += a * w.z; acc3 += a * w.w;
        }
        __syncthreads();
    }

    // ---- biases + activations + cell update
    const int unit = j0 + q;
    acc0 += b_ih[0 * HIDDEN + unit] + b_hh[0 * HIDDEN + unit];
    acc1 += b_ih[1 * HIDDEN + unit] + b_hh[1 * HIDDEN + unit];
    acc2 += b_ih[2 * HIDDEN + unit] + b_hh[2 * HIDDEN + unit];
    acc3 += b_ih[3 * HIDDEN + unit] + b_hh[3 * HIDDEN + unit];

    float ig = 1.f / (1.f + expf(-acc0));
    float fg = 1.f / (1.f + expf(-acc1));
    float gg = tanhf(acc2);
    float og = 1.f / (1.f + expf(-acc3));

    const int ci = m * HIDDEN + unit;
    float c = fg * g_c[ci] + ig * gg;
    g_c[ci] = c;
    g_h[wb][ci] = og * tanhf(c);
}

// ---------------- fc: logits GEMM + write + fused argmax ----------------
// grid = 250 CTAs, tile [64 m x 128 n], K=512 in chunks of 64.
// thread (tx = tid&15 -> 8 n, ty = tid>>4 -> 4 m), 32 accumulators.
__global__ __launch_bounds__(256) void fc_kernel(
    const float* __restrict__ fc_w,
    const float* __restrict__ fc_b,
    float* __restrict__ out,
    int t)
{
    __shared__ float Hs[64][64];    // [k][b]   16 KB
    __shared__ float Ws[64][128];   // [k][n]   32 KB  (total exactly 48 KB)

    const int tid = threadIdx.x;
    const int n0  = blockIdx.x * 128;
    const int hb  = (t & 1) ^ 1;    // h buffer written by this step's lstm
    const int tx  = tid & 15;
    const int ty  = tid >> 4;

    float acc[4][8];
    #pragma unroll
    for (int i = 0; i < 4; i++)
        #pragma unroll
        for (int j = 0; j < 8; j++) acc[i][j] = 0.f;

    for (int kc = 0; kc < 8; kc++) {
        const int kbase = kc * 64;
        // ---- Hs: h[b][kbase..kbase+63] -> Hs[k][b]
        {
            const int b   = tid >> 2;
            const int klo = (tid & 3) * 16;
            const float* src = g_h[hb] + b * HIDDEN + kbase + klo;
            #pragma unroll
            for (int i = 0; i < 4; i++) {
                float4 v = *(const float4*)(src + i * 4);
                int k = klo + i * 4;
                Hs[k][b] = v.x; Hs[k+1][b] = v.y; Hs[k+2][b] = v.z; Hs[k+3][b] = v.w;
            }
        }
        // ---- Ws: fc_w[n0+n][kbase..kbase+63] -> Ws[k][n]
        {
            const int n   = tid >> 1;
            const int klo = (tid & 1) * 32;
            const float* src = fc_w + (size_t)(n0 + n) * HIDDEN + kbase + klo;
            #pragma unroll
            for (int i = 0; i < 8; i++) {
                float4 v = *(const float4*)(src + i * 4);
                int k = klo + i * 4;
                Ws[k][n] = v.x; Ws[k+1][n] = v.y; Ws[k+2][n] = v.z; Ws[k+3][n] = v.w;
            }
        }
        __syncthreads();

        #pragma unroll 8
        for (int k = 0; k < 64; k++) {
            float4 a  = *(const float4*)&Hs[k][ty * 4];
            float4 w0 = *(const float4*)&Ws[k][tx * 8];
            float4 w1 = *(const float4*)&Ws[k][tx * 8 + 4];
            float av[4] = {a.x, a.y, a.z, a.w};
            float wv[8] = {w0.x, w0.y, w0.z, w0.w, w1.x, w1.y, w1.z, w1.w};
            #pragma unroll
            for (int mi = 0; mi < 4; mi++)
                #pragma unroll
                for (int ni = 0; ni < 8; ni++)
                    acc[mi][ni] += av[mi] * wv[ni];
        }
        __syncthreads();
    }

    // ---- bias
    float4 b0 = *(const float4*)(fc_b + n0 + tx * 8);
    float4 b1 = *(const float4*)(fc_b + n0 + tx * 8 + 4);
    float bv[8] = {b0.x, b0.y, b0.z, b0.w, b1.x, b1.y, b1.z, b1.w};
    #pragma unroll
    for (int mi = 0; mi < 4; mi++)
        #pragma unroll
        for (int ni = 0; ni < 8; ni++)
            acc[mi][ni] += bv[ni];

    // ---- write logits: out[b][t][v]
    #pragma unroll
    for (int mi = 0; mi < 4; mi++) {
        const int m = ty * 4 + mi;
        float* dst = out + (size_t)m * TSTEPS * VOCAB + (size_t)t * VOCAB + n0 + tx * 8;
        *(float4*)(dst)     = make_float4(acc[mi][0], acc[mi][1], acc[mi][2], acc[mi][3]);
        *(float4*)(dst + 4) = make_float4(acc[mi][4], acc[mi][5], acc[mi][6], acc[mi][7]);
    }

    // ---- fused argmax: local -> 16-lane shfl reduce -> global atomicMax
    float bestv[4];
    int   bestn[4];
    #pragma unroll
    for (int mi = 0; mi < 4; mi++) {
        bestv[mi] = acc[mi][0];
        bestn[mi] = n0 + tx * 8;
        #pragma unroll
        for (int ni = 1; ni < 8; ni++) {
            int n = n0 + tx * 8 + ni;
            float v = acc[mi][ni];
            if (v > bestv[mi] || (v == bestv[mi] && n < bestn[mi])) {
                bestv[mi] = v; bestn[mi] = n;
            }
        }
    }
    #pragma unroll
    for (int off = 8; off > 0; off >>= 1) {
        #pragma unroll
        for (int mi = 0; mi < 4; mi++) {
            float ov = __shfl_xor_sync(0xffffffffu, bestv[mi], off);
            int   on = __shfl_xor_sync(0xffffffffu, bestn[mi], off);
            if (ov > bestv[mi] || (ov == bestv[mi] && on < bestn[mi])) {
                bestv[mi] = ov; bestn[mi] = on;
            }
        }
    }
    if (tx == 0) {
        #pragma unroll
        for (int mi = 0; mi < 4; mi++) {
            const int m = ty * 4 + mi;
            unsigned long long key =
                ((unsigned long long)ford(bestv[mi]) << 32) |
                (unsigned long long)(unsigned int)(~bestn[mi]);
            atomicMax(&g_amax[t * BATCH + m], key);
        }
    }
}

// ---------------- launch ----------------
extern "C" void kernel_launch(void* const* d_in, const int* in_sizes, int n_in,
                              void* d_out, int out_size) {
    const float* hidden    = (const float*)d_in[0];
    const float* cell      = (const float*)d_in[1];
    /* d_in[2] = max_length (compile-time TSTEPS) */
    const int*   start_tok = (const int*)d_in[3];
    const float* embedding = (const float*)d_in[4];
    const float* w_ih      = (const float*)d_in[5];
    const float* w_hh      = (const float*)d_in[6];
    const float* b_ih      = (const float*)d_in[7];
    const float* b_hh      = (const float*)d_in[8];
    const float* fc_w      = (const float*)d_in[9];
    const float* fc_b      = (const float*)d_in[10];
    float* out = (float*)d_out;

    init_kernel<<<128, 256>>>(hidden, cell);
    for (int t = 0; t < TSTEPS; t++) {
        lstm_step_kernel<<<128, 256>>>(embedding, w_ih, w_hh, b_ih, b_hh, start_tok, t);
        fc_kernel<<<VOCAB / 128, 256>>>(fc_w, fc_b, out, t);
    }
}